// round 1
// baseline (speedup 1.0000x reference)
#include <cuda_runtime.h>
#include <cstdint>
#include <cstddef>

#define BS   4
#define SEQ  1024
#define NH   16
#define HD   64
#define DM   1024
#define ER_L 2047
#define ER_PITCH 2049

// Scratch projections in [b,h,s,d] layout (device globals: allocation-free rule)
__device__ float g_q[BS*NH*SEQ*HD];
__device__ float g_k[BS*NH*SEQ*HD];
__device__ float g_v[BS*NH*SEQ*HD];
// Fallback logits buffer if harness output turns out to be 'out' only
__device__ float g_scratch[(size_t)BS*NH*SEQ*SEQ];

__device__ __forceinline__ uint32_t f2t(float x) {
    uint32_t u;
    asm("cvt.rna.tf32.f32 %0, %1;" : "=r"(u) : "f"(x));
    return u;
}

__device__ __forceinline__ void mma8(float* c, const uint32_t* a, const uint32_t* b) {
    asm volatile(
        "mma.sync.aligned.m16n8k8.row.col.f32.tf32.tf32.f32 "
        "{%0,%1,%2,%3},{%4,%5,%6,%7},{%8,%9},{%0,%1,%2,%3};"
        : "+f"(c[0]), "+f"(c[1]), "+f"(c[2]), "+f"(c[3])
        : "r"(a[0]), "r"(a[1]), "r"(a[2]), "r"(a[3]), "r"(b[0]), "r"(b[1]));
}

// ---------------------------------------------------------------------------
// Kernel 1: C = A @ W^T + bias, scattered to [b,h,s,d] layout.
// A: [4096,1024] row-major, W: [1024,1024] row-major (rows = out features).
// Block tile 128x128, K-chunk 32, 8 warps (2x4), warp tile 64x32, tf32 mma.
// ---------------------------------------------------------------------------
__global__ void __launch_bounds__(256) proj_kernel(
    const float* __restrict__ A, const float* __restrict__ W,
    const float* __restrict__ bias, float* __restrict__ outp)
{
    __shared__ float a_s[128][36];
    __shared__ float w_s[128][36];
    const int tid  = threadIdx.x;
    const int warp = tid >> 5, lane = tid & 31;
    const int g = lane >> 2, t = lane & 3;
    const int wm = warp >> 2, wn = warp & 3;
    const int m_blk = blockIdx.y * 128;
    const int n_blk = blockIdx.x * 128;

    float acc[4][4][4];
#pragma unroll
    for (int mi = 0; mi < 4; mi++)
#pragma unroll
        for (int ni = 0; ni < 4; ni++)
#pragma unroll
            for (int x = 0; x < 4; x++) acc[mi][ni][x] = 0.f;

    const int lrow = tid >> 3;
    const int lcol = (tid & 7) << 2;

    for (int kc = 0; kc < DM; kc += 32) {
        __syncthreads();
#pragma unroll
        for (int i = 0; i < 4; i++) {
            int r = lrow + i * 32;
            float4 av = *(const float4*)(A + (size_t)(m_blk + r) * DM + kc + lcol);
            *(float2*)&a_s[r][lcol]     = make_float2(av.x, av.y);
            *(float2*)&a_s[r][lcol + 2] = make_float2(av.z, av.w);
            float4 wv = *(const float4*)(W + (size_t)(n_blk + r) * DM + kc + lcol);
            *(float2*)&w_s[r][lcol]     = make_float2(wv.x, wv.y);
            *(float2*)&w_s[r][lcol + 2] = make_float2(wv.z, wv.w);
        }
        __syncthreads();
#pragma unroll
        for (int ks = 0; ks < 4; ks++) {
            const int kk = ks * 8;
            uint32_t a[4][4], b[4][2];
#pragma unroll
            for (int mi = 0; mi < 4; mi++) {
                int r0 = wm * 64 + mi * 16;
                a[mi][0] = f2t(a_s[r0 + g][kk + t]);
                a[mi][1] = f2t(a_s[r0 + g + 8][kk + t]);
                a[mi][2] = f2t(a_s[r0 + g][kk + t + 4]);
                a[mi][3] = f2t(a_s[r0 + g + 8][kk + t + 4]);
            }
#pragma unroll
            for (int ni = 0; ni < 4; ni++) {
                int c0 = wn * 32 + ni * 8;
                b[ni][0] = f2t(w_s[c0 + g][kk + t]);
                b[ni][1] = f2t(w_s[c0 + g][kk + t + 4]);
            }
#pragma unroll
            for (int mi = 0; mi < 4; mi++)
#pragma unroll
                for (int ni = 0; ni < 4; ni++)
                    mma8(acc[mi][ni], a[mi], b[ni]);
        }
    }

#pragma unroll
    for (int mi = 0; mi < 4; mi++) {
        int row0 = m_blk + wm * 64 + mi * 16 + g;
        int row1 = row0 + 8;
#pragma unroll
        for (int ni = 0; ni < 4; ni++) {
            int col = n_blk + wn * 32 + ni * 8 + 2 * t;
            float b0 = bias[col], b1 = bias[col + 1];
            int h_i = col >> 6, d_i = col & 63;
            {
                int b_i = row0 >> 10, s_i = row0 & 1023;
                size_t addr = ((size_t)(b_i * NH + h_i) * SEQ + s_i) * HD + d_i;
                *(float2*)(outp + addr) = make_float2(acc[mi][ni][0] + b0, acc[mi][ni][1] + b1);
            }
            {
                int b_i = row1 >> 10, s_i = row1 & 1023;
                size_t addr = ((size_t)(b_i * NH + h_i) * SEQ + s_i) * HD + d_i;
                *(float2*)(outp + addr) = make_float2(acc[mi][ni][2] + b0, acc[mi][ni][3] + b1);
            }
        }
    }
}

// ---------------------------------------------------------------------------
// Kernel 2: per (b,h,s-tile of 64) fused scores + rel-pos + softmax + attn
// write + out = attn @ v.  4 warps, each owning 16 s-rows.
// Srel[s,t] = q[s] . Er[1023 + t - s]  (derived from the skew trick).
// Pass 1: raw logits -> attn buffer + exact online row max/sum.
// Pass 2: normalize (attn final) + P@V via tf32 mma.
// ---------------------------------------------------------------------------
__global__ void __launch_bounds__(128) attn_kernel(
    const float* __restrict__ gq, const float* __restrict__ gk,
    const float* __restrict__ gv, const float* __restrict__ Er,
    float* __restrict__ out_f, float* __restrict__ attn_o)
{
    extern __shared__ float smem_f[];
    float* q_s  = smem_f;                          // [64][68]
    float* kv_s = smem_f + 64 * 68;                // [64][68]
    float* er_s = smem_f + 2 * 64 * 68;            // [128][68] (pass1) / p_s (pass2)
    float* R_s  = smem_f + 2 * 64 * 68 + 128 * 68; // [64][132]
    float* p_s  = er_s;

    const int tid  = threadIdx.x;
    const int warp = tid >> 5, lane = tid & 31;
    const int g = lane >> 2, t = lane & 3;
    const int rs = warp << 4;
    const int s0 = blockIdx.x << 6;
    const int bh = blockIdx.y;
    const int h  = bh & 15;

    const float* qp  = gq + ((size_t)bh * SEQ + s0) * HD;
    const float* kp  = gk + (size_t)bh * SEQ * HD;
    const float* vp  = gv + (size_t)bh * SEQ * HD;
    const float* erp = Er + (size_t)h * ER_PITCH * HD;
    float* attn_p = attn_o + ((size_t)bh * SEQ + s0) * SEQ;

    // load q tile (64x64)
    for (int i = tid; i < 64 * 16; i += 128) {
        int r = i >> 4, c = (i & 15) << 2;
        float4 v4 = *(const float4*)(qp + (size_t)r * HD + c);
        *(float2*)&q_s[r * 68 + c]     = make_float2(v4.x, v4.y);
        *(float2*)&q_s[r * 68 + c + 2] = make_float2(v4.z, v4.w);
    }
    __syncthreads();

    // q A-fragments live in registers across the whole kernel
    uint32_t qa[8][4];
#pragma unroll
    for (int ks = 0; ks < 8; ks++) {
        int kk = ks * 8;
        qa[ks][0] = f2t(q_s[(rs + g) * 68 + kk + t]);
        qa[ks][1] = f2t(q_s[(rs + g + 8) * 68 + kk + t]);
        qa[ks][2] = f2t(q_s[(rs + g) * 68 + kk + t + 4]);
        qa[ks][3] = f2t(q_s[(rs + g + 8) * 68 + kk + t + 4]);
    }

    float m0 = -1e30f, m1 = -1e30f, sum0 = 0.f, sum1 = 0.f;

    // ---------------- pass 1: logits + online stats ----------------
    for (int tt = 0; tt < 16; tt++) {
        const int t0 = tt << 6;
        __syncthreads();
        for (int i = tid; i < 64 * 16; i += 128) {       // k tile
            int r = i >> 4, c = (i & 15) << 2;
            float4 v4 = *(const float4*)(kp + (size_t)(t0 + r) * HD + c);
            *(float2*)&kv_s[r * 68 + c]     = make_float2(v4.x, v4.y);
            *(float2*)&kv_s[r * 68 + c + 2] = make_float2(v4.z, v4.w);
        }
        const int r0 = 960 + t0 - s0;                    // Er band base (>=0)
        for (int i = tid; i < 128 * 16; i += 128) {      // Er tile (128 rows)
            int r = i >> 4, c = (i & 15) << 2;
            int er_row = r0 + r;
            float4 v4 = make_float4(0.f, 0.f, 0.f, 0.f);
            if (er_row < ER_L) v4 = *(const float4*)(erp + (size_t)er_row * HD + c);
            *(float2*)&er_s[r * 68 + c]     = make_float2(v4.x, v4.y);
            *(float2*)&er_s[r * 68 + c + 2] = make_float2(v4.z, v4.w);
        }
        __syncthreads();

        // R = q @ Er^T  (64 x 128), per-warp rows, staged via smem
#pragma unroll 4
        for (int nf = 0; nf < 16; nf++) {
            float c4[4] = {0.f, 0.f, 0.f, 0.f};
#pragma unroll
            for (int ks = 0; ks < 8; ks++) {
                int kk = ks * 8;
                uint32_t bb[2];
                bb[0] = f2t(er_s[(nf * 8 + g) * 68 + kk + t]);
                bb[1] = f2t(er_s[(nf * 8 + g) * 68 + kk + t + 4]);
                mma8(c4, qa[ks], bb);
            }
            *(float2*)&R_s[(rs + g) * 132 + nf * 8 + 2 * t]     = make_float2(c4[0], c4[1]);
            *(float2*)&R_s[(rs + g + 8) * 132 + nf * 8 + 2 * t] = make_float2(c4[2], c4[3]);
        }
        __syncwarp();

        // scores = (q @ k^T + diag-gathered R) / 8
        float sc[8][4];
        const int sA = rs + g, sB = rs + g + 8;
#pragma unroll
        for (int nf = 0; nf < 8; nf++) {
            float c4[4] = {0.f, 0.f, 0.f, 0.f};
#pragma unroll
            for (int ks = 0; ks < 8; ks++) {
                int kk = ks * 8;
                uint32_t bb[2];
                bb[0] = f2t(kv_s[(nf * 8 + g) * 68 + kk + t]);
                bb[1] = f2t(kv_s[(nf * 8 + g) * 68 + kk + t + 4]);
                mma8(c4, qa[ks], bb);
            }
            int tp = nf * 8 + 2 * t;
            sc[nf][0] = (c4[0] + R_s[sA * 132 + 63 + tp     - sA]) * 0.125f;
            sc[nf][1] = (c4[1] + R_s[sA * 132 + 63 + tp + 1 - sA]) * 0.125f;
            sc[nf][2] = (c4[2] + R_s[sB * 132 + 63 + tp     - sB]) * 0.125f;
            sc[nf][3] = (c4[3] + R_s[sB * 132 + 63 + tp + 1 - sB]) * 0.125f;
            *(float2*)&attn_p[(size_t)sA * SEQ + t0 + tp] = make_float2(sc[nf][0], sc[nf][1]);
            *(float2*)&attn_p[(size_t)sB * SEQ + t0 + tp] = make_float2(sc[nf][2], sc[nf][3]);
        }

        // online max / sumexp per row (quad-reduce)
        float tm0 = -1e30f, tm1 = -1e30f;
#pragma unroll
        for (int nf = 0; nf < 8; nf++) {
            tm0 = fmaxf(tm0, fmaxf(sc[nf][0], sc[nf][1]));
            tm1 = fmaxf(tm1, fmaxf(sc[nf][2], sc[nf][3]));
        }
        tm0 = fmaxf(tm0, __shfl_xor_sync(0xffffffffu, tm0, 1));
        tm0 = fmaxf(tm0, __shfl_xor_sync(0xffffffffu, tm0, 2));
        tm1 = fmaxf(tm1, __shfl_xor_sync(0xffffffffu, tm1, 1));
        tm1 = fmaxf(tm1, __shfl_xor_sync(0xffffffffu, tm1, 2));
        float nm0 = fmaxf(m0, tm0), nm1 = fmaxf(m1, tm1);
        float ts0 = 0.f, ts1 = 0.f;
#pragma unroll
        for (int nf = 0; nf < 8; nf++) {
            ts0 += __expf(sc[nf][0] - nm0) + __expf(sc[nf][1] - nm0);
            ts1 += __expf(sc[nf][2] - nm1) + __expf(sc[nf][3] - nm1);
        }
        ts0 += __shfl_xor_sync(0xffffffffu, ts0, 1);
        ts0 += __shfl_xor_sync(0xffffffffu, ts0, 2);
        ts1 += __shfl_xor_sync(0xffffffffu, ts1, 1);
        ts1 += __shfl_xor_sync(0xffffffffu, ts1, 2);
        sum0 = sum0 * __expf(m0 - nm0) + ts0;
        sum1 = sum1 * __expf(m1 - nm1) + ts1;
        m0 = nm0; m1 = nm1;
    }

    const float inv0 = 1.f / sum0, inv1 = 1.f / sum1;

    // ---------------- pass 2: normalize + out = P @ V ----------------
    float oacc[8][4];
#pragma unroll
    for (int ni = 0; ni < 8; ni++)
#pragma unroll
        for (int x = 0; x < 4; x++) oacc[ni][x] = 0.f;

    const int sA = rs + g, sB = rs + g + 8;
    for (int tt = 0; tt < 16; tt++) {
        const int t0 = tt << 6;
        __syncthreads();
        for (int i = tid; i < 64 * 16; i += 128) {       // v tile
            int r = i >> 4, c = (i & 15) << 2;
            float4 v4 = *(const float4*)(vp + (size_t)(t0 + r) * HD + c);
            *(float2*)&kv_s[r * 68 + c]     = make_float2(v4.x, v4.y);
            *(float2*)&kv_s[r * 68 + c + 2] = make_float2(v4.z, v4.w);
        }
        __syncthreads();

#pragma unroll
        for (int nf = 0; nf < 8; nf++) {
            int tp = nf * 8 + 2 * t;
            float2 vA = *(float2*)&attn_p[(size_t)sA * SEQ + t0 + tp];
            float2 vB = *(float2*)&attn_p[(size_t)sB * SEQ + t0 + tp];
            vA.x = __expf(vA.x - m0) * inv0;  vA.y = __expf(vA.y - m0) * inv0;
            vB.x = __expf(vB.x - m1) * inv1;  vB.y = __expf(vB.y - m1) * inv1;
            *(float2*)&attn_p[(size_t)sA * SEQ + t0 + tp] = vA;   // final attn
            *(float2*)&attn_p[(size_t)sB * SEQ + t0 + tp] = vB;
            *(float2*)&p_s[sA * 68 + tp] = vA;                    // stage for A-frags
            *(float2*)&p_s[sB * 68 + tp] = vB;
        }
        __syncwarp();

#pragma unroll
        for (int ks = 0; ks < 8; ks++) {
            int kk = ks * 8;
            uint32_t pa[4];
            pa[0] = f2t(p_s[sA * 68 + kk + t]);
            pa[1] = f2t(p_s[sB * 68 + kk + t]);
            pa[2] = f2t(p_s[sA * 68 + kk + t + 4]);
            pa[3] = f2t(p_s[sB * 68 + kk + t + 4]);
#pragma unroll
            for (int ni = 0; ni < 8; ni++) {
                uint32_t bb[2];
                bb[0] = f2t(kv_s[(kk + t) * 68 + ni * 8 + g]);
                bb[1] = f2t(kv_s[(kk + t + 4) * 68 + ni * 8 + g]);
                mma8(oacc[ni], pa, bb);
            }
        }
    }

    // store out in [b, s, h*64+d]
    const int b_i = bh >> 4;
    const int gsA = s0 + sA, gsB = s0 + sB;
#pragma unroll
    for (int ni = 0; ni < 8; ni++) {
        int col = h * HD + ni * 8 + 2 * t;
        *(float2*)(out_f + ((size_t)b_i * SEQ + gsA) * DM + col) = make_float2(oacc[ni][0], oacc[ni][1]);
        *(float2*)(out_f + ((size_t)b_i * SEQ + gsB) * DM + col) = make_float2(oacc[ni][2], oacc[ni][3]);
    }
}

// ---------------------------------------------------------------------------
extern "C" void kernel_launch(void* const* d_in, const int* in_sizes, int n_in,
                              void* d_out, int out_size)
{
    const float* query = (const float*)d_in[0];
    const float* key   = (const float*)d_in[1];
    const float* value = (const float*)d_in[2];
    const float* Wq = (const float*)d_in[3];
    const float* bq = (const float*)d_in[4];
    const float* Wk = (const float*)d_in[5];
    const float* bk = (const float*)d_in[6];
    const float* Wv = (const float*)d_in[7];
    const float* bv = (const float*)d_in[8];
    const float* Er = (const float*)d_in[9];
    float* outp = (float*)d_out;

    float *gq, *gk, *gv, *gs;
    cudaGetSymbolAddress((void**)&gq, g_q);
    cudaGetSymbolAddress((void**)&gk, g_k);
    cudaGetSymbolAddress((void**)&gv, g_v);
    cudaGetSymbolAddress((void**)&gs, g_scratch);

    // Output is the tuple (out, attn) flattened; fall back to scratch if not.
    float* attn = (out_size > BS * SEQ * DM) ? (outp + (size_t)BS * SEQ * DM) : gs;

    dim3 gp(DM / 128, (BS * SEQ) / 128);
    proj_kernel<<<gp, 256>>>(query, Wq, bq, gq);
    proj_kernel<<<gp, 256>>>(key,   Wk, bk, gk);
    proj_kernel<<<gp, 256>>>(value, Wv, bv, gv);

    int smem_bytes = (2 * 64 * 68 + 128 * 68 + 64 * 132) * 4;
    cudaFuncSetAttribute(attn_kernel, cudaFuncAttributeMaxDynamicSharedMemorySize, smem_bytes);
    attn_kernel<<<dim3(SEQ / 64, BS * NH), 128, smem_bytes>>>(gq, gk, gv, Er, outp, attn);
}

// round 2
// speedup vs baseline: 1.3407x; 1.3407x over previous
#include <cuda_runtime.h>
#include <cstdint>
#include <cstddef>

#define BS   4
#define SEQ  1024
#define NH   16
#define HD   64
#define DM   1024
#define ER_L 2047
#define ER_PITCH 2049

__device__ float g_q[BS*NH*SEQ*HD];
__device__ float g_k[BS*NH*SEQ*HD];
__device__ float g_v[BS*NH*SEQ*HD];
__device__ float g_scratch[(size_t)BS*NH*SEQ*SEQ];

__device__ __forceinline__ uint32_t f2t(float x) {
    uint32_t u;
    asm("cvt.rna.tf32.f32 %0, %1;" : "=r"(u) : "f"(x));
    return u;
}

__device__ __forceinline__ void mma8(float* c, const uint32_t* a, const uint32_t* b) {
    asm volatile(
        "mma.sync.aligned.m16n8k8.row.col.f32.tf32.tf32.f32 "
        "{%0,%1,%2,%3},{%4,%5,%6,%7},{%8,%9},{%0,%1,%2,%3};"
        : "+f"(c[0]), "+f"(c[1]), "+f"(c[2]), "+f"(c[3])
        : "r"(a[0]), "r"(a[1]), "r"(a[2]), "r"(a[3]), "r"(b[0]), "r"(b[1]));
}

__device__ __forceinline__ uint32_t s2u(const void* p) {
    uint32_t a;
    asm("{ .reg .u64 t; cvta.to.shared.u64 t, %1; cvt.u32.u64 %0, t; }" : "=r"(a) : "l"(p));
    return a;
}

// cp.async 16B with runtime src-size (0 => zero-fill, no gmem access)
__device__ __forceinline__ void cpa16(uint32_t dst, const float* src, int nbytes) {
    asm volatile("cp.async.ca.shared.global [%0], [%1], 16, %2;"
                 :: "r"(dst), "l"(src), "r"(nbytes));
}
__device__ __forceinline__ void cpa_wait_all() {
    asm volatile("cp.async.wait_all;" ::: "memory");
}

// ---------------------------------------------------------------------------
// Projections: C = A @ W^T + bias scattered to [b,h,s,d]. grid.z selects q/k/v.
// ---------------------------------------------------------------------------
__global__ void __launch_bounds__(256) proj_kernel(
    const float* __restrict__ A0, const float* __restrict__ A1, const float* __restrict__ A2,
    const float* __restrict__ W0, const float* __restrict__ W1, const float* __restrict__ W2,
    const float* __restrict__ b0, const float* __restrict__ b1, const float* __restrict__ b2,
    float* __restrict__ o0, float* __restrict__ o1, float* __restrict__ o2)
{
    const int z = blockIdx.z;
    const float* A    = (z == 0) ? A0 : (z == 1) ? A1 : A2;
    const float* W    = (z == 0) ? W0 : (z == 1) ? W1 : W2;
    const float* bias = (z == 0) ? b0 : (z == 1) ? b1 : b2;
    float* outp       = (z == 0) ? o0 : (z == 1) ? o1 : o2;

    __shared__ float a_s[128][36];
    __shared__ float w_s[128][36];
    const int tid  = threadIdx.x;
    const int warp = tid >> 5, lane = tid & 31;
    const int g = lane >> 2, t = lane & 3;
    const int wm = warp >> 2, wn = warp & 3;
    const int m_blk = blockIdx.y * 128;
    const int n_blk = blockIdx.x * 128;

    float acc[4][4][4];
#pragma unroll
    for (int mi = 0; mi < 4; mi++)
#pragma unroll
        for (int ni = 0; ni < 4; ni++)
#pragma unroll
            for (int x = 0; x < 4; x++) acc[mi][ni][x] = 0.f;

    const int lrow = tid >> 3;
    const int lcol = (tid & 7) << 2;
    const uint32_t a_u = s2u(&a_s[0][0]);
    const uint32_t w_u = s2u(&w_s[0][0]);

    for (int kc = 0; kc < DM; kc += 32) {
        __syncthreads();
#pragma unroll
        for (int i = 0; i < 4; i++) {
            int r = lrow + i * 32;
            cpa16(a_u + (r * 36 + lcol) * 4, A + (size_t)(m_blk + r) * DM + kc + lcol, 16);
            cpa16(w_u + (r * 36 + lcol) * 4, W + (size_t)(n_blk + r) * DM + kc + lcol, 16);
        }
        cpa_wait_all();
        __syncthreads();
#pragma unroll
        for (int ks = 0; ks < 4; ks++) {
            const int kk = ks * 8;
            uint32_t a[4][4], b[4][2];
#pragma unroll
            for (int mi = 0; mi < 4; mi++) {
                int r0 = wm * 64 + mi * 16;
                a[mi][0] = f2t(a_s[r0 + g][kk + t]);
                a[mi][1] = f2t(a_s[r0 + g + 8][kk + t]);
                a[mi][2] = f2t(a_s[r0 + g][kk + t + 4]);
                a[mi][3] = f2t(a_s[r0 + g + 8][kk + t + 4]);
            }
#pragma unroll
            for (int ni = 0; ni < 4; ni++) {
                int c0 = wn * 32 + ni * 8;
                b[ni][0] = f2t(w_s[c0 + g][kk + t]);
                b[ni][1] = f2t(w_s[c0 + g][kk + t + 4]);
            }
#pragma unroll
            for (int mi = 0; mi < 4; mi++)
#pragma unroll
                for (int ni = 0; ni < 4; ni++)
                    mma8(acc[mi][ni], a[mi], b[ni]);
        }
    }

#pragma unroll
    for (int mi = 0; mi < 4; mi++) {
        int row0 = m_blk + wm * 64 + mi * 16 + g;
        int row1 = row0 + 8;
#pragma unroll
        for (int ni = 0; ni < 4; ni++) {
            int col = n_blk + wn * 32 + ni * 8 + 2 * t;
            float bb0 = bias[col], bb1 = bias[col + 1];
            int h_i = col >> 6, d_i = col & 63;
            {
                int b_i = row0 >> 10, s_i = row0 & 1023;
                size_t addr = ((size_t)(b_i * NH + h_i) * SEQ + s_i) * HD + d_i;
                *(float2*)(outp + addr) = make_float2(acc[mi][ni][0] + bb0, acc[mi][ni][1] + bb1);
            }
            {
                int b_i = row1 >> 10, s_i = row1 & 1023;
                size_t addr = ((size_t)(b_i * NH + h_i) * SEQ + s_i) * HD + d_i;
                *(float2*)(outp + addr) = make_float2(acc[mi][ni][2] + bb0, acc[mi][ni][3] + bb1);
            }
        }
    }
}

// ---------------------------------------------------------------------------
// Fused attention. 4 warps, 64 s-rows/block.
// Rolling relative-position band: R_s circular buffer over 128 Er columns;
// only 64 new Er rows GEMMed per t-tile (127 on the first tile).
// Pass 1: raw logits -> attn buffer + exact online row max/sum.
// Pass 2: normalize (final attn) + out = P@V.
// smem: k_s 64x68 | er_s/v_s 64x68 | R_s/p_s 64x132  = 68.6 KB -> 3 blocks/SM.
// ---------------------------------------------------------------------------
__global__ void __launch_bounds__(128, 3) attn_kernel(
    const float* __restrict__ gq, const float* __restrict__ gk,
    const float* __restrict__ gv, const float* __restrict__ Er,
    float* __restrict__ out_f, float* __restrict__ attn_o)
{
    extern __shared__ float smem_f[];
    float* k_s  = smem_f;                 // [64][68]
    float* er_s = smem_f + 64 * 68;       // [64][68]  (pass2: v_s)
    float* R_s  = smem_f + 2 * 64 * 68;   // [64][132] (pass2: p_s, stride 68)
    float* v_s  = er_s;
    float* p_s  = R_s;

    const int tid  = threadIdx.x;
    const int warp = tid >> 5, lane = tid & 31;
    const int g = lane >> 2, t = lane & 3;
    const int rs = warp << 4;
    const int s0 = blockIdx.x << 6;
    const int bh = blockIdx.y;
    const int h  = bh & 15;

    const float* qp  = gq + ((size_t)bh * SEQ + s0) * HD;
    const float* kp  = gk + (size_t)bh * SEQ * HD;
    const float* vp  = gv + (size_t)bh * SEQ * HD;
    const float* erp = Er + (size_t)h * ER_PITCH * HD;
    float* attn_p = attn_o + ((size_t)bh * SEQ + s0) * SEQ;

    const uint32_t k_u  = s2u(k_s);
    const uint32_t er_u = s2u(er_s);
    const int base_abs = 960 - s0;        // er_abs = base_abs + e,  e = local band coord

    // ---- q tile -> fragments (staged through k_s) ----
    for (int i = tid; i < 64 * 16; i += 128) {
        int r = i >> 4, c = (i & 15) << 2;
        cpa16(k_u + (r * 68 + c) * 4, qp + (size_t)r * HD + c, 16);
    }
    cpa_wait_all();
    __syncthreads();
    uint32_t qa[8][4];
    const int sA = rs + g, sB = rs + g + 8;
#pragma unroll
    for (int ks = 0; ks < 8; ks++) {
        int kk = ks * 8;
        qa[ks][0] = f2t(k_s[sA * 68 + kk + t]);
        qa[ks][1] = f2t(k_s[sB * 68 + kk + t]);
        qa[ks][2] = f2t(k_s[sA * 68 + kk + t + 4]);
        qa[ks][3] = f2t(k_s[sB * 68 + kk + t + 4]);
    }

    float m0 = -1e30f, m1 = -1e30f, sum0 = 0.f, sum1 = 0.f;

    // ---------------- pass 1 ----------------
    for (int tt = 0; tt < 16; tt++) {
        const int t0 = tt << 6;
        __syncthreads();
        // k tile async
        for (int i = tid; i < 64 * 16; i += 128) {
            int r = i >> 4, c = (i & 15) << 2;
            cpa16(k_u + (r * 68 + c) * 4, kp + (size_t)(t0 + r) * HD + c, 16);
        }
        // new er block
        int es = (tt == 0) ? 0 : ((tt + 1) << 6);
#pragma unroll 1
        for (int blk = 0; blk < 2; blk++) {
            for (int i = tid; i < 64 * 16; i += 128) {
                int r = i >> 4, c = (i & 15) << 2;
                int abs_r = base_abs + es + r;
                cpa16(er_u + (r * 68 + c) * 4, erp + (size_t)abs_r * HD + c,
                      (abs_r < ER_L) ? 16 : 0);
            }
            cpa_wait_all();
            __syncthreads();
            // R += q @ er_blk^T  (64 new columns, circular store)
#pragma unroll
            for (int nf = 0; nf < 8; nf++) {
                float c4[4] = {0.f, 0.f, 0.f, 0.f};
#pragma unroll
                for (int ks = 0; ks < 8; ks++) {
                    int kk = ks * 8;
                    uint32_t bb[2];
                    bb[0] = f2t(er_s[(nf * 8 + g) * 68 + kk + t]);
                    bb[1] = f2t(er_s[(nf * 8 + g) * 68 + kk + t + 4]);
                    mma8(c4, qa[ks], bb);
                }
                int e0 = es + nf * 8 + 2 * t;    // even -> no wrap inside float2
                int j0 = e0 & 127;
                *(float2*)&R_s[sA * 132 + j0] = make_float2(c4[0], c4[1]);
                *(float2*)&R_s[sB * 132 + j0] = make_float2(c4[2], c4[3]);
            }
            if (tt != 0 || blk == 1) break;
            __syncthreads();                     // er_s reload on tt==0
            es = 64;
        }

        // scores = (q@k^T + diag(R)) / 8
        float sc[8][4];
#pragma unroll
        for (int nf = 0; nf < 8; nf++) {
            float c4[4] = {0.f, 0.f, 0.f, 0.f};
#pragma unroll
            for (int ks = 0; ks < 8; ks++) {
                int kk = ks * 8;
                uint32_t bb[2];
                bb[0] = f2t(k_s[(nf * 8 + g) * 68 + kk + t]);
                bb[1] = f2t(k_s[(nf * 8 + g) * 68 + kk + t + 4]);
                mma8(c4, qa[ks], bb);
            }
            int tp = nf * 8 + 2 * t;
            int cb = t0 + 63 + tp;               // e = cb - s  (t0 = 64*tt)
            sc[nf][0] = (c4[0] + R_s[sA * 132 + ((cb     - sA) & 127)]) * 0.125f;
            sc[nf][1] = (c4[1] + R_s[sA * 132 + ((cb + 1 - sA) & 127)]) * 0.125f;
            sc[nf][2] = (c4[2] + R_s[sB * 132 + ((cb     - sB) & 127)]) * 0.125f;
            sc[nf][3] = (c4[3] + R_s[sB * 132 + ((cb + 1 - sB) & 127)]) * 0.125f;
            *(float2*)&attn_p[(size_t)sA * SEQ + t0 + tp] = make_float2(sc[nf][0], sc[nf][1]);
            *(float2*)&attn_p[(size_t)sB * SEQ + t0 + tp] = make_float2(sc[nf][2], sc[nf][3]);
        }

        // online stats (quad reduce, rows sA / sB)
        float tm0 = -1e30f, tm1 = -1e30f;
#pragma unroll
        for (int nf = 0; nf < 8; nf++) {
            tm0 = fmaxf(tm0, fmaxf(sc[nf][0], sc[nf][1]));
            tm1 = fmaxf(tm1, fmaxf(sc[nf][2], sc[nf][3]));
        }
        tm0 = fmaxf(tm0, __shfl_xor_sync(0xffffffffu, tm0, 1));
        tm0 = fmaxf(tm0, __shfl_xor_sync(0xffffffffu, tm0, 2));
        tm1 = fmaxf(tm1, __shfl_xor_sync(0xffffffffu, tm1, 1));
        tm1 = fmaxf(tm1, __shfl_xor_sync(0xffffffffu, tm1, 2));
        float nm0 = fmaxf(m0, tm0), nm1 = fmaxf(m1, tm1);
        float ts0 = 0.f, ts1 = 0.f;
#pragma unroll
        for (int nf = 0; nf < 8; nf++) {
            ts0 += __expf(sc[nf][0] - nm0) + __expf(sc[nf][1] - nm0);
            ts1 += __expf(sc[nf][2] - nm1) + __expf(sc[nf][3] - nm1);
        }
        ts0 += __shfl_xor_sync(0xffffffffu, ts0, 1);
        ts0 += __shfl_xor_sync(0xffffffffu, ts0, 2);
        ts1 += __shfl_xor_sync(0xffffffffu, ts1, 1);
        ts1 += __shfl_xor_sync(0xffffffffu, ts1, 2);
        sum0 = sum0 * __expf(m0 - nm0) + ts0;
        sum1 = sum1 * __expf(m1 - nm1) + ts1;
        m0 = nm0; m1 = nm1;
    }

    const float inv0 = 1.f / sum0, inv1 = 1.f / sum1;

    // ---------------- pass 2 ----------------
    float oacc[8][4];
#pragma unroll
    for (int ni = 0; ni < 8; ni++)
#pragma unroll
        for (int x = 0; x < 4; x++) oacc[ni][x] = 0.f;

    for (int tt = 0; tt < 16; tt++) {
        const int t0 = tt << 6;
        __syncthreads();
        for (int i = tid; i < 64 * 16; i += 128) {   // v tile (aliases er_s)
            int r = i >> 4, c = (i & 15) << 2;
            cpa16(er_u + (r * 68 + c) * 4, vp + (size_t)(t0 + r) * HD + c, 16);
        }
        // normalize logits -> final attn + stage P (same-thread RAW on gmem)
#pragma unroll
        for (int nf = 0; nf < 8; nf++) {
            int tp = nf * 8 + 2 * t;
            float2 vA = *(float2*)&attn_p[(size_t)sA * SEQ + t0 + tp];
            float2 vB = *(float2*)&attn_p[(size_t)sB * SEQ + t0 + tp];
            vA.x = __expf(vA.x - m0) * inv0;  vA.y = __expf(vA.y - m0) * inv0;
            vB.x = __expf(vB.x - m1) * inv1;  vB.y = __expf(vB.y - m1) * inv1;
            *(float2*)&attn_p[(size_t)sA * SEQ + t0 + tp] = vA;
            *(float2*)&attn_p[(size_t)sB * SEQ + t0 + tp] = vB;
            *(float2*)&p_s[sA * 68 + tp] = vA;
            *(float2*)&p_s[sB * 68 + tp] = vB;
        }
        cpa_wait_all();
        __syncthreads();

#pragma unroll
        for (int ks = 0; ks < 8; ks++) {
            int kk = ks * 8;
            uint32_t pa[4];
            pa[0] = f2t(p_s[sA * 68 + kk + t]);
            pa[1] = f2t(p_s[sB * 68 + kk + t]);
            pa[2] = f2t(p_s[sA * 68 + kk + t + 4]);
            pa[3] = f2t(p_s[sB * 68 + kk + t + 4]);
#pragma unroll
            for (int ni = 0; ni < 8; ni++) {
                uint32_t bb[2];
                bb[0] = f2t(v_s[(kk + t) * 68 + ni * 8 + g]);
                bb[1] = f2t(v_s[(kk + t + 4) * 68 + ni * 8 + g]);
                mma8(oacc[ni], pa, bb);
            }
        }
    }

    const int b_i = bh >> 4;
    const int gsA = s0 + sA, gsB = s0 + sB;
#pragma unroll
    for (int ni = 0; ni < 8; ni++) {
        int col = h * HD + ni * 8 + 2 * t;
        *(float2*)(out_f + ((size_t)b_i * SEQ + gsA) * DM + col) = make_float2(oacc[ni][0], oacc[ni][1]);
        *(float2*)(out_f + ((size_t)b_i * SEQ + gsB) * DM + col) = make_float2(oacc[ni][2], oacc[ni][3]);
    }
}

// ---------------------------------------------------------------------------
extern "C" void kernel_launch(void* const* d_in, const int* in_sizes, int n_in,
                              void* d_out, int out_size)
{
    const float* query = (const float*)d_in[0];
    const float* key   = (const float*)d_in[1];
    const float* value = (const float*)d_in[2];
    const float* Wq = (const float*)d_in[3];
    const float* bq = (const float*)d_in[4];
    const float* Wk = (const float*)d_in[5];
    const float* bk = (const float*)d_in[6];
    const float* Wv = (const float*)d_in[7];
    const float* bv = (const float*)d_in[8];
    const float* Er = (const float*)d_in[9];
    float* outp = (float*)d_out;

    float *gq, *gk, *gv, *gs;
    cudaGetSymbolAddress((void**)&gq, g_q);
    cudaGetSymbolAddress((void**)&gk, g_k);
    cudaGetSymbolAddress((void**)&gv, g_v);
    cudaGetSymbolAddress((void**)&gs, g_scratch);

    float* attn = (out_size > BS * SEQ * DM) ? (outp + (size_t)BS * SEQ * DM) : gs;

    dim3 gp(DM / 128, (BS * SEQ) / 128, 3);
    proj_kernel<<<gp, 256>>>(query, key, value, Wq, Wk, Wv, bq, bk, bv, gq, gk, gv);

    int smem_bytes = (2 * 64 * 68 + 64 * 132) * 4;
    cudaFuncSetAttribute(attn_kernel, cudaFuncAttributeMaxDynamicSharedMemorySize, smem_bytes);
    attn_kernel<<<dim3(SEQ / 64, BS * NH), 128, smem_bytes>>>(gq, gk, gv, Er, outp, attn);
}

// round 3
// speedup vs baseline: 2.3015x; 1.7167x over previous
#include <cuda_runtime.h>
#include <cstdint>
#include <cstddef>

#define BS   4
#define SEQ  1024
#define NH   16
#define HD   64
#define DM   1024
#define ER_L 2047
#define ER_PITCH 2049

__device__ float g_q[BS*NH*SEQ*HD];
__device__ float g_k[BS*NH*SEQ*HD];
__device__ float g_v[BS*NH*SEQ*HD];
__device__ float g_er[NH*ER_PITCH*HD];
__device__ float g_scratch[(size_t)BS*NH*SEQ*SEQ];

__device__ __forceinline__ uint32_t f2t(float x) {
    uint32_t u;
    asm("cvt.rna.tf32.f32 %0, %1;" : "=r"(u) : "f"(x));
    return u;
}
__device__ __forceinline__ float rndt(float x) { return __uint_as_float(f2t(x)); }

__device__ __forceinline__ void mma8(float* c, const uint32_t* a, const uint32_t* b) {
    asm volatile(
        "mma.sync.aligned.m16n8k8.row.col.f32.tf32.tf32.f32 "
        "{%0,%1,%2,%3},{%4,%5,%6,%7},{%8,%9},{%0,%1,%2,%3};"
        : "+f"(c[0]), "+f"(c[1]), "+f"(c[2]), "+f"(c[3])
        : "r"(a[0]), "r"(a[1]), "r"(a[2]), "r"(a[3]), "r"(b[0]), "r"(b[1]));
}

__device__ __forceinline__ uint32_t s2u(const void* p) {
    uint32_t a;
    asm("{ .reg .u64 t; cvta.to.shared.u64 t, %1; cvt.u32.u64 %0, t; }" : "=r"(a) : "l"(p));
    return a;
}

__device__ __forceinline__ void cpa16(uint32_t dst, const float* src, int nbytes) {
    asm volatile("cp.async.ca.shared.global [%0], [%1], 16, %2;"
                 :: "r"(dst), "l"(src), "r"(nbytes));
}
__device__ __forceinline__ void cpa_commit() {
    asm volatile("cp.async.commit_group;" ::: "memory");
}
__device__ __forceinline__ void cpa_wait0() {
    asm volatile("cp.async.wait_group 0;" ::: "memory");
}
__device__ __forceinline__ void cpa_wait1() {
    asm volatile("cp.async.wait_group 1;" ::: "memory");
}

// ---------------------------------------------------------------------------
// Pre-round Er to tf32 (one-shot, tiny).  16*2049*64 floats, float4 grain.
// ---------------------------------------------------------------------------
__global__ void er_round_kernel(const float* __restrict__ er, float* __restrict__ o) {
    int i = (blockIdx.x * blockDim.x + threadIdx.x) * 4;
    float4 v = *(const float4*)(er + i);
    v.x = rndt(v.x); v.y = rndt(v.y); v.z = rndt(v.z); v.w = rndt(v.w);
    *(float4*)(o + i) = v;
}

// ---------------------------------------------------------------------------
// Projections: C = A @ W^T + bias, tf32-rounded, scattered to [b,h,s,d].
// ---------------------------------------------------------------------------
__global__ void __launch_bounds__(256) proj_kernel(
    const float* __restrict__ A0, const float* __restrict__ A1, const float* __restrict__ A2,
    const float* __restrict__ W0, const float* __restrict__ W1, const float* __restrict__ W2,
    const float* __restrict__ b0, const float* __restrict__ b1, const float* __restrict__ b2,
    float* __restrict__ o0, float* __restrict__ o1, float* __restrict__ o2)
{
    const int z = blockIdx.z;
    const float* A    = (z == 0) ? A0 : (z == 1) ? A1 : A2;
    const float* W    = (z == 0) ? W0 : (z == 1) ? W1 : W2;
    const float* bias = (z == 0) ? b0 : (z == 1) ? b1 : b2;
    float* outp       = (z == 0) ? o0 : (z == 1) ? o1 : o2;

    __shared__ float a_s[128][36];
    __shared__ float w_s[128][36];
    const int tid  = threadIdx.x;
    const int warp = tid >> 5, lane = tid & 31;
    const int g = lane >> 2, t = lane & 3;
    const int wm = warp >> 2, wn = warp & 3;
    const int m_blk = blockIdx.y * 128;
    const int n_blk = blockIdx.x * 128;

    float acc[4][4][4];
#pragma unroll
    for (int mi = 0; mi < 4; mi++)
#pragma unroll
        for (int ni = 0; ni < 4; ni++)
#pragma unroll
            for (int x = 0; x < 4; x++) acc[mi][ni][x] = 0.f;

    const int lrow = tid >> 3;
    const int lcol = (tid & 7) << 2;
    const uint32_t a_u = s2u(&a_s[0][0]);
    const uint32_t w_u = s2u(&w_s[0][0]);

    for (int kc = 0; kc < DM; kc += 32) {
        __syncthreads();
#pragma unroll
        for (int i = 0; i < 4; i++) {
            int r = lrow + i * 32;
            cpa16(a_u + (r * 36 + lcol) * 4, A + (size_t)(m_blk + r) * DM + kc + lcol, 16);
            cpa16(w_u + (r * 36 + lcol) * 4, W + (size_t)(n_blk + r) * DM + kc + lcol, 16);
        }
        cpa_commit();
        cpa_wait0();
        __syncthreads();
#pragma unroll
        for (int ks = 0; ks < 4; ks++) {
            const int kk = ks * 8;
            uint32_t a[4][4], b[4][2];
#pragma unroll
            for (int mi = 0; mi < 4; mi++) {
                int r0 = wm * 64 + mi * 16;
                a[mi][0] = f2t(a_s[r0 + g][kk + t]);
                a[mi][1] = f2t(a_s[r0 + g + 8][kk + t]);
                a[mi][2] = f2t(a_s[r0 + g][kk + t + 4]);
                a[mi][3] = f2t(a_s[r0 + g + 8][kk + t + 4]);
            }
#pragma unroll
            for (int ni = 0; ni < 4; ni++) {
                int c0 = wn * 32 + ni * 8;
                b[ni][0] = f2t(w_s[c0 + g][kk + t]);
                b[ni][1] = f2t(w_s[c0 + g][kk + t + 4]);
            }
#pragma unroll
            for (int mi = 0; mi < 4; mi++)
#pragma unroll
                for (int ni = 0; ni < 4; ni++)
                    mma8(acc[mi][ni], a[mi], b[ni]);
        }
    }

#pragma unroll
    for (int mi = 0; mi < 4; mi++) {
        int row0 = m_blk + wm * 64 + mi * 16 + g;
        int row1 = row0 + 8;
#pragma unroll
        for (int ni = 0; ni < 4; ni++) {
            int col = n_blk + wn * 32 + ni * 8 + 2 * t;
            float bb0 = bias[col], bb1 = bias[col + 1];
            int h_i = col >> 6, d_i = col & 63;
            {
                int b_i = row0 >> 10, s_i = row0 & 1023;
                size_t addr = ((size_t)(b_i * NH + h_i) * SEQ + s_i) * HD + d_i;
                *(float2*)(outp + addr) = make_float2(rndt(acc[mi][ni][0] + bb0), rndt(acc[mi][ni][1] + bb1));
            }
            {
                int b_i = row1 >> 10, s_i = row1 & 1023;
                size_t addr = ((size_t)(b_i * NH + h_i) * SEQ + s_i) * HD + d_i;
                *(float2*)(outp + addr) = make_float2(rndt(acc[mi][ni][2] + bb0), rndt(acc[mi][ni][3] + bb1));
            }
        }
    }
}

// ---------------------------------------------------------------------------
// Fused attention: operands pre-rounded to tf32 -> plain LDS into mma.
// Software-pipelined cp.async groups: er(next) issued after R-mma, k(next)
// after scores; pass 2 double-buffers V across the idle k_s/er_s regions.
// ---------------------------------------------------------------------------
__global__ void __launch_bounds__(128, 3) attn_kernel(
    const float* __restrict__ gq, const float* __restrict__ gk,
    const float* __restrict__ gv, const float* __restrict__ ger,
    float* __restrict__ out_f, float* __restrict__ attn_o)
{
    extern __shared__ float smem_f[];
    float* k_s  = smem_f;                 // [64][68]   pass2: v buf (even tiles)
    float* er_s = smem_f + 64 * 68;       // [64][68]   pass2: v buf (odd tiles)
    float* R_s  = smem_f + 2 * 64 * 68;   // [64][132]  pass2: p_s

    const int tid  = threadIdx.x;
    const int warp = tid >> 5, lane = tid & 31;
    const int g = lane >> 2, t = lane & 3;
    const int rs = warp << 4;
    const int s0 = blockIdx.x << 6;
    const int bh = blockIdx.y;
    const int h  = bh & 15;

    const float* qp  = gq + ((size_t)bh * SEQ + s0) * HD;
    const float* kp  = gk + (size_t)bh * SEQ * HD;
    const float* vp  = gv + (size_t)bh * SEQ * HD;
    const float* erp = ger + (size_t)h * ER_PITCH * HD;
    float* attn_p = attn_o + ((size_t)bh * SEQ + s0) * SEQ;

    const uint32_t k_u  = s2u(k_s);
    const uint32_t er_u = s2u(er_s);
    const int base_abs = 960 - s0;
    const int sA = rs + g, sB = rs + g + 8;

#define ISSUE_ER(bi) do {                                                     \
        int es_ = (bi) << 6;                                                  \
        for (int i = tid; i < 64 * 16; i += 128) {                            \
            int r_ = i >> 4, c_ = (i & 15) << 2;                              \
            int ar_ = base_abs + es_ + r_;                                    \
            cpa16(er_u + (r_ * 68 + c_) * 4, erp + (size_t)ar_ * HD + c_,     \
                  (ar_ < ER_L) ? 16 : 0);                                     \
        }                                                                     \
        cpa_commit();                                                         \
    } while (0)

#define ISSUE_K(ti) do {                                                      \
        int t0_ = (ti) << 6;                                                  \
        for (int i = tid; i < 64 * 16; i += 128) {                            \
            int r_ = i >> 4, c_ = (i & 15) << 2;                              \
            cpa16(k_u + (r_ * 68 + c_) * 4, kp + (size_t)(t0_ + r_) * HD + c_, 16); \
        }                                                                     \
        cpa_commit();                                                         \
    } while (0)

#define R_MMA(bi) do {                                                        \
        int es_ = (bi) << 6;                                                  \
        _Pragma("unroll")                                                     \
        for (int nf = 0; nf < 8; nf++) {                                      \
            float c4[4] = {0.f, 0.f, 0.f, 0.f};                               \
            _Pragma("unroll")                                                 \
            for (int ks = 0; ks < 8; ks++) {                                  \
                int kk = ks * 8;                                              \
                uint32_t bb[2];                                               \
                bb[0] = __float_as_uint(er_s[(nf * 8 + g) * 68 + kk + t]);    \
                bb[1] = __float_as_uint(er_s[(nf * 8 + g) * 68 + kk + t + 4]);\
                mma8(c4, qa[ks], bb);                                         \
            }                                                                 \
            int j0 = (es_ + nf * 8 + 2 * t) & 127;                            \
            *(float2*)&R_s[sA * 132 + j0] = make_float2(c4[0], c4[1]);        \
            *(float2*)&R_s[sB * 132 + j0] = make_float2(c4[2], c4[3]);        \
        }                                                                     \
    } while (0)

    // ---- q tile -> fragments (staged through er_s; pre-rounded) ----
    for (int i = tid; i < 64 * 16; i += 128) {
        int r = i >> 4, c = (i & 15) << 2;
        cpa16(er_u + (r * 68 + c) * 4, qp + (size_t)r * HD + c, 16);
    }
    cpa_commit();
    cpa_wait0();
    __syncthreads();
    uint32_t qa[8][4];
#pragma unroll
    for (int ks = 0; ks < 8; ks++) {
        int kk = ks * 8;
        qa[ks][0] = __float_as_uint(er_s[sA * 68 + kk + t]);
        qa[ks][1] = __float_as_uint(er_s[sB * 68 + kk + t]);
        qa[ks][2] = __float_as_uint(er_s[sA * 68 + kk + t + 4]);
        qa[ks][3] = __float_as_uint(er_s[sB * 68 + kk + t + 4]);
    }
    __syncthreads();

    // ---- prologue: Er block 0 -> R cols [0,64); then pipeline primed ----
    ISSUE_ER(0);
    cpa_wait0();
    __syncthreads();
    R_MMA(0);
    __syncthreads();
    ISSUE_ER(1);        // pending: ER1
    ISSUE_K(0);         // pending: ER1, K0

    float m0 = -1e30f, m1 = -1e30f, sum0 = 0.f, sum1 = 0.f;

    // ---------------- pass 1 ----------------
    for (int tt = 0; tt < 16; tt++) {
        const int t0 = tt << 6;

        cpa_wait1();            // ER(tt+1) done (K(tt) may still be in flight)
        __syncthreads();
        R_MMA(tt + 1);
        __syncthreads();
        if (tt < 15) { ISSUE_ER(tt + 2); cpa_wait1(); }  // K(tt) done
        else         { cpa_wait0(); }
        __syncthreads();

        // scores = (q@k^T + diag(R)) / 8
        float sc[8][4];
#pragma unroll
        for (int nf = 0; nf < 8; nf++) {
            float c4[4] = {0.f, 0.f, 0.f, 0.f};
#pragma unroll
            for (int ks = 0; ks < 8; ks++) {
                int kk = ks * 8;
                uint32_t bb[2];
                bb[0] = __float_as_uint(k_s[(nf * 8 + g) * 68 + kk + t]);
                bb[1] = __float_as_uint(k_s[(nf * 8 + g) * 68 + kk + t + 4]);
                mma8(c4, qa[ks], bb);
            }
            int tp = nf * 8 + 2 * t;
            int cb = t0 + 63 + tp;
            sc[nf][0] = (c4[0] + R_s[sA * 132 + ((cb     - sA) & 127)]) * 0.125f;
            sc[nf][1] = (c4[1] + R_s[sA * 132 + ((cb + 1 - sA) & 127)]) * 0.125f;
            sc[nf][2] = (c4[2] + R_s[sB * 132 + ((cb     - sB) & 127)]) * 0.125f;
            sc[nf][3] = (c4[3] + R_s[sB * 132 + ((cb + 1 - sB) & 127)]) * 0.125f;
            *(float2*)&attn_p[(size_t)sA * SEQ + t0 + tp] = make_float2(sc[nf][0], sc[nf][1]);
            *(float2*)&attn_p[(size_t)sB * SEQ + t0 + tp] = make_float2(sc[nf][2], sc[nf][3]);
        }

        // online stats
        float tm0 = -1e30f, tm1 = -1e30f;
#pragma unroll
        for (int nf = 0; nf < 8; nf++) {
            tm0 = fmaxf(tm0, fmaxf(sc[nf][0], sc[nf][1]));
            tm1 = fmaxf(tm1, fmaxf(sc[nf][2], sc[nf][3]));
        }
        tm0 = fmaxf(tm0, __shfl_xor_sync(0xffffffffu, tm0, 1));
        tm0 = fmaxf(tm0, __shfl_xor_sync(0xffffffffu, tm0, 2));
        tm1 = fmaxf(tm1, __shfl_xor_sync(0xffffffffu, tm1, 1));
        tm1 = fmaxf(tm1, __shfl_xor_sync(0xffffffffu, tm1, 2));
        float nm0 = fmaxf(m0, tm0), nm1 = fmaxf(m1, tm1);
        float ts0 = 0.f, ts1 = 0.f;
#pragma unroll
        for (int nf = 0; nf < 8; nf++) {
            ts0 += __expf(sc[nf][0] - nm0) + __expf(sc[nf][1] - nm0);
            ts1 += __expf(sc[nf][2] - nm1) + __expf(sc[nf][3] - nm1);
        }
        ts0 += __shfl_xor_sync(0xffffffffu, ts0, 1);
        ts0 += __shfl_xor_sync(0xffffffffu, ts0, 2);
        ts1 += __shfl_xor_sync(0xffffffffu, ts1, 1);
        ts1 += __shfl_xor_sync(0xffffffffu, ts1, 2);
        sum0 = sum0 * __expf(m0 - nm0) + ts0;
        sum1 = sum1 * __expf(m1 - nm1) + ts1;
        m0 = nm0; m1 = nm1;

        __syncthreads();
        if (tt < 15) ISSUE_K(tt + 1);
    }

    const float inv0 = 1.f / sum0, inv1 = 1.f / sum1;
    float* p_s = R_s;

    // ---------------- pass 2 ----------------
    float oacc[8][4];
#pragma unroll
    for (int ni = 0; ni < 8; ni++)
#pragma unroll
        for (int x = 0; x < 4; x++) oacc[ni][x] = 0.f;

    // v(0) -> k_s
    for (int i = tid; i < 64 * 16; i += 128) {
        int r = i >> 4, c = (i & 15) << 2;
        cpa16(k_u + (r * 68 + c) * 4, vp + (size_t)r * HD + c, 16);
    }
    cpa_commit();

    for (int tt = 0; tt < 16; tt++) {
        const int t0 = tt << 6;
        const float* vb = (tt & 1) ? er_s : k_s;
        const uint32_t vu_next = (tt & 1) ? k_u : er_u;

        if (tt < 15) {
            for (int i = tid; i < 64 * 16; i += 128) {
                int r = i >> 4, c = (i & 15) << 2;
                cpa16(vu_next + (r * 68 + c) * 4, vp + (size_t)(t0 + 64 + r) * HD + c, 16);
            }
            cpa_commit();
        }

        // prefetch logits
        float2 fA[8], fB[8];
#pragma unroll
        for (int nf = 0; nf < 8; nf++) {
            int tp = nf * 8 + 2 * t;
            fA[nf] = *(float2*)&attn_p[(size_t)sA * SEQ + t0 + tp];
            fB[nf] = *(float2*)&attn_p[(size_t)sB * SEQ + t0 + tp];
        }
        if (tt < 15) cpa_wait1(); else cpa_wait0();
        __syncthreads();

#pragma unroll
        for (int nf = 0; nf < 8; nf++) {
            int tp = nf * 8 + 2 * t;
            float2 vA = fA[nf], vB = fB[nf];
            vA.x = __expf(vA.x - m0) * inv0;  vA.y = __expf(vA.y - m0) * inv0;
            vB.x = __expf(vB.x - m1) * inv1;  vB.y = __expf(vB.y - m1) * inv1;
            *(float2*)&attn_p[(size_t)sA * SEQ + t0 + tp] = vA;
            *(float2*)&attn_p[(size_t)sB * SEQ + t0 + tp] = vB;
            *(float2*)&p_s[sA * 68 + tp] = make_float2(rndt(vA.x), rndt(vA.y));
            *(float2*)&p_s[sB * 68 + tp] = make_float2(rndt(vB.x), rndt(vB.y));
        }
        __syncthreads();

#pragma unroll
        for (int ks = 0; ks < 8; ks++) {
            int kk = ks * 8;
            uint32_t pa[4];
            pa[0] = __float_as_uint(p_s[sA * 68 + kk + t]);
            pa[1] = __float_as_uint(p_s[sB * 68 + kk + t]);
            pa[2] = __float_as_uint(p_s[sA * 68 + kk + t + 4]);
            pa[3] = __float_as_uint(p_s[sB * 68 + kk + t + 4]);
#pragma unroll
            for (int ni = 0; ni < 8; ni++) {
                uint32_t bb[2];
                bb[0] = __float_as_uint(vb[(kk + t) * 68 + ni * 8 + g]);
                bb[1] = __float_as_uint(vb[(kk + t + 4) * 68 + ni * 8 + g]);
                mma8(oacc[ni], pa, bb);
            }
        }
        __syncthreads();
    }

    const int b_i = bh >> 4;
    const int gsA = s0 + sA, gsB = s0 + sB;
#pragma unroll
    for (int ni = 0; ni < 8; ni++) {
        int col = h * HD + ni * 8 + 2 * t;
        *(float2*)(out_f + ((size_t)b_i * SEQ + gsA) * DM + col) = make_float2(oacc[ni][0], oacc[ni][1]);
        *(float2*)(out_f + ((size_t)b_i * SEQ + gsB) * DM + col) = make_float2(oacc[ni][2], oacc[ni][3]);
    }
#undef ISSUE_ER
#undef ISSUE_K
#undef R_MMA
}

// ---------------------------------------------------------------------------
extern "C" void kernel_launch(void* const* d_in, const int* in_sizes, int n_in,
                              void* d_out, int out_size)
{
    const float* query = (const float*)d_in[0];
    const float* key   = (const float*)d_in[1];
    const float* value = (const float*)d_in[2];
    const float* Wq = (const float*)d_in[3];
    const float* bq = (const float*)d_in[4];
    const float* Wk = (const float*)d_in[5];
    const float* bk = (const float*)d_in[6];
    const float* Wv = (const float*)d_in[7];
    const float* bv = (const float*)d_in[8];
    const float* Er = (const float*)d_in[9];
    float* outp = (float*)d_out;

    float *gq, *gk, *gv, *ger, *gs;
    cudaGetSymbolAddress((void**)&gq, g_q);
    cudaGetSymbolAddress((void**)&gk, g_k);
    cudaGetSymbolAddress((void**)&gv, g_v);
    cudaGetSymbolAddress((void**)&ger, g_er);
    cudaGetSymbolAddress((void**)&gs, g_scratch);

    float* attn = (out_size > BS * SEQ * DM) ? (outp + (size_t)BS * SEQ * DM) : gs;

    er_round_kernel<<<2049, 256>>>(Er, ger);

    dim3 gp(DM / 128, (BS * SEQ) / 128, 3);
    proj_kernel<<<gp, 256>>>(query, key, value, Wq, Wk, Wv, bq, bk, bv, gq, gk, gv);

    int smem_bytes = (2 * 64 * 68 + 64 * 132) * 4;
    cudaFuncSetAttribute(attn_kernel, cudaFuncAttributeMaxDynamicSharedMemorySize, smem_bytes);
    attn_kernel<<<dim3(SEQ / 64, BS * NH), 128, smem_bytes>>>(gq, gk, gv, ger, outp, attn);
}